// round 13
// baseline (speedup 1.0000x reference)
#include <cuda_runtime.h>
#include <math.h>
#include <stdint.h>

#define SS 2
#define NATOM 2048
#define CC 128
#define HH 8
#define DHD 16
#define CPD 16
#define TT 512
#define CTD 384
#define NBLK 3
#define WIN 128
#define NQB (NATOM/32)
#define EPS 1e-5f
#define SNC (SS*NATOM*CC)
#define NC (NATOM*CC)
#define ZBS (HH*NATOM*WIN)

#define EPI_NONE 0
#define EPI_SIG  1

#define AP 36
#define BP 72

// ---------------- scratch ----------------
__device__ __align__(16) float g_sn  [NBLK*NC];
__device__ __align__(16) float g_sn2 [NBLK*NC];
__device__ __align__(16) float g_g1  [NBLK*NC];
__device__ __align__(16) float g_sh1 [NBLK*NC];
__device__ __align__(16) float g_og1 [NBLK*NC];
__device__ __align__(16) float g_g2  [NBLK*NC];
__device__ __align__(16) float g_sh2 [NBLK*NC];
__device__ __align__(16) float g_og2 [NBLK*NC];
__device__ __align__(16) float g_a   [SNC];
__device__ __align__(16) float g_a1  [SNC];
__device__ __align__(16) float g_q   [SNC];
__device__ __align__(16) float g_k   [SNC];
__device__ __align__(16) float g_v   [SNC];
__device__ __align__(16) float g_attg[SNC];
__device__ __align__(16) float g_o   [SNC];
__device__ __align__(16) float g_zb  [NBLK*ZBS];
__device__ __align__(16) float g_hid [SS*NATOM*2*CC];
__device__ __align__(16) float g_qtok[SS*NATOM*CTD];

// ---------------- helpers ----------------
__device__ __forceinline__ void blockReduce2_128(float& a, float& b) {
    #pragma unroll
    for (int o = 16; o; o >>= 1) {
        a += __shfl_xor_sync(0xffffffffu, a, o);
        b += __shfl_xor_sync(0xffffffffu, b, o);
    }
    __shared__ float sa[4], sb[4];
    int w = threadIdx.x >> 5;
    if ((threadIdx.x & 31) == 0) { sa[w] = a; sb[w] = b; }
    __syncthreads();
    a = sa[0] + sa[1] + sa[2] + sa[3];
    b = sb[0] + sb[1] + sb[2] + sb[3];
}

__device__ __forceinline__ float sigf(float x) { return 1.0f / (1.0f + __expf(-x)); }

__device__ __forceinline__ unsigned f2tf(float f) {
    unsigned u; asm("cvt.rna.tf32.f32 %0, %1;" : "=r"(u) : "f"(f)); return u;
}

__device__ __forceinline__ void mma_tf32(float (&d)[4], const unsigned (&a)[4], const unsigned (&b)[2]) {
    asm volatile(
        "mma.sync.aligned.m16n8k8.row.col.f32.tf32.tf32.f32 "
        "{%0,%1,%2,%3}, {%4,%5,%6,%7}, {%8,%9}, {%0,%1,%2,%3};\n"
        : "+f"(d[0]), "+f"(d[1]), "+f"(d[2]), "+f"(d[3])
        : "r"(a[0]), "r"(a[1]), "r"(a[2]), "r"(a[3]), "r"(b[0]), "r"(b[1]));
}

// ---------------- GEMM building blocks ----------------
struct ARegs { float4 v[4]; };
struct BRegs { float4 v[2]; };

__device__ __forceinline__ void loadA(ARegs& ra, const float* __restrict__ X,
                                      int m0, int k0, int ld) {
    int t = threadIdx.x;
    int r = t >> 1, cb = (t & 1) * 16;
    const float4* src = reinterpret_cast<const float4*>(X + (size_t)(m0 + r) * ld + k0 + cb);
    #pragma unroll
    for (int i = 0; i < 4; i++) ra.v[i] = src[i];
}

__device__ __forceinline__ void loadA_mul(ARegs& ra, const float* __restrict__ X1,
                                          const float* __restrict__ X2, int m0, int k0, int ld) {
    int t = threadIdx.x;
    int r = t >> 1, cb = (t & 1) * 16;
    size_t base = (size_t)(m0 + r) * ld + k0 + cb;
    const float4* s1 = reinterpret_cast<const float4*>(X1 + base);
    const float4* s2 = reinterpret_cast<const float4*>(X2 + base);
    #pragma unroll
    for (int i = 0; i < 4; i++) {
        float4 a = s1[i], b = s2[i];
        ra.v[i] = make_float4(a.x*b.x, a.y*b.y, a.z*b.z, a.w*b.w);
    }
}

__device__ __forceinline__ void storeA(unsigned (*As)[AP], const ARegs& ra) {
    int t = threadIdx.x;
    int r = t >> 1, cb = (t & 1) * 16;
    #pragma unroll
    for (int i = 0; i < 4; i++) {
        float4 v = ra.v[i];
        uint4 u = make_uint4(f2tf(v.x), f2tf(v.y), f2tf(v.z), f2tf(v.w));
        *reinterpret_cast<uint4*>(&As[r][cb + 4*i]) = u;
    }
}

__device__ __forceinline__ void loadB(BRegs& rb, const float* __restrict__ W,
                                      int k0, int n0, int ld) {
    int t = threadIdx.x;
    int k = t >> 3, nb = (t & 7) * 8;
    const float4* src = reinterpret_cast<const float4*>(W + (size_t)(k0 + k) * ld + n0 + nb);
    rb.v[0] = src[0]; rb.v[1] = src[1];
}

__device__ __forceinline__ void storeB(unsigned (*Bs)[BP], const BRegs& rb) {
    int t = threadIdx.x;
    int k = t >> 3, nb = (t & 7) * 8;
    float4 v0 = rb.v[0], v1 = rb.v[1];
    *reinterpret_cast<uint4*>(&Bs[k][nb])     = make_uint4(f2tf(v0.x), f2tf(v0.y), f2tf(v0.z), f2tf(v0.w));
    *reinterpret_cast<uint4*>(&Bs[k][nb + 4]) = make_uint4(f2tf(v1.x), f2tf(v1.y), f2tf(v1.z), f2tf(v1.w));
}

__device__ __forceinline__ void stageA(unsigned (*As)[AP], const float* __restrict__ X,
                                       int m0, int k0, int ld) {
    ARegs ra; loadA(ra, X, m0, k0, ld); storeA(As, ra);
}
__device__ __forceinline__ void stageB(unsigned (*Bs)[BP], const float* __restrict__ W,
                                       int k0, int n0, int ld) {
    BRegs rb; loadB(rb, W, k0, n0, ld); storeB(Bs, rb);
}

__device__ __forceinline__ void compute32(const unsigned (*As)[AP], const unsigned (*Bs)[BP],
                                          float (*acc)[4][4], int wm, int wn, int g, int tig) {
    #pragma unroll
    for (int ks = 0; ks < 4; ks++) {
        int k8 = ks * 8;
        unsigned a[2][4], b[4][2];
        #pragma unroll
        for (int i = 0; i < 2; i++) {
            int rb = wm * 32 + i * 16;
            a[i][0] = As[rb + g    ][k8 + tig];
            a[i][1] = As[rb + g + 8][k8 + tig];
            a[i][2] = As[rb + g    ][k8 + tig + 4];
            a[i][3] = As[rb + g + 8][k8 + tig + 4];
        }
        #pragma unroll
        for (int j = 0; j < 4; j++) {
            int nb = wn * 32 + j * 8;
            b[j][0] = Bs[k8 + tig    ][nb + g];
            b[j][1] = Bs[k8 + tig + 4][nb + g];
        }
        #pragma unroll
        for (int i = 0; i < 2; i++)
            #pragma unroll
            for (int j = 0; j < 4; j++)
                mma_tf32(acc[i][j], a[i], b[j]);
    }
}

#define EPILOGUE_LOOP(BODY)                                                    \
    _Pragma("unroll")                                                          \
    for (int i = 0; i < 2; i++) {                                              \
        _Pragma("unroll")                                                      \
        for (int j = 0; j < 4; j++) {                                          \
            _Pragma("unroll")                                                  \
            for (int r = 0; r < 4; r++) {                                      \
                int m = m0 + wm*32 + i*16 + g + ((r >> 1) ? 8 : 0);            \
                int n = n0 + wn*32 + j*8 + 2*tig + (r & 1);                    \
                BODY                                                           \
            }                                                                  \
        }                                                                      \
    }

struct GB {
    const float* X[6];
    const float* W[6];
    const float* B[6];
    float*       Y[6];
    int          epi[6];
};

// batched gemm, register double-buffered. Ncol=K=CC.
__global__ void tgemm_b(GB gb) {
    __shared__ unsigned As[128][AP];
    __shared__ unsigned Bs[32][BP];
    int z = blockIdx.z;
    const float* X = gb.X[z];
    const float* W = gb.W[z];
    int m0 = blockIdx.x * 128, n0 = blockIdx.y * 64;
    int tid = threadIdx.x, lane = tid & 31, w = tid >> 5;
    int g = lane >> 2, tig = lane & 3, wm = w >> 1, wn = w & 1;
    float acc[2][4][4] = {};
    ARegs ra; BRegs rb;
    loadA(ra, X, m0, 0, CC);
    loadB(rb, W, 0, n0, CC);
    #pragma unroll
    for (int c = 0; c < 4; c++) {
        storeA(As, ra);
        storeB(Bs, rb);
        __syncthreads();
        if (c < 3) {
            loadA(ra, X, m0, (c + 1) * 32, CC);
            loadB(rb, W, (c + 1) * 32, n0, CC);
        }
        compute32(As, Bs, acc, wm, wn, g, tig);
        __syncthreads();
    }
    const float* bias = gb.B[z];
    float* Y = gb.Y[z];
    int epi = gb.epi[z];
    EPILOGUE_LOOP({
        float v = acc[i][j][r];
        if (bias) v += bias[n];
        if (epi == EPI_SIG) v = sigf(v);
        Y[(size_t)m * CC + n] = v;
    })
}

// sn-projection batch for ONE block: z = 0..5, base pointers offset by blk.
struct GBS {
    const float* W[6];
    const float* B[6];
    float*       Y[6];
    int          epi[6];
};

__global__ void tgemm_sn_all(GBS gs, int blk) {
    __shared__ unsigned As[128][AP];
    __shared__ unsigned Bs[32][BP];
    int z = blockIdx.z;
    const float* X = (z < 3 ? g_sn : g_sn2) + (size_t)blk * NC;
    const float* W = gs.W[z] + (size_t)blk * CC * CC;
    int m0 = blockIdx.x * 128, n0 = blockIdx.y * 64;
    int tid = threadIdx.x, lane = tid & 31, w = tid >> 5;
    int g = lane >> 2, tig = lane & 3, wm = w >> 1, wn = w & 1;
    float acc[2][4][4] = {};
    ARegs ra; BRegs rb;
    loadA(ra, X, m0, 0, CC);
    loadB(rb, W, 0, n0, CC);
    #pragma unroll
    for (int c = 0; c < 4; c++) {
        storeA(As, ra);
        storeB(Bs, rb);
        __syncthreads();
        if (c < 3) {
            loadA(ra, X, m0, (c + 1) * 32, CC);
            loadB(rb, W, (c + 1) * 32, n0, CC);
        }
        compute32(As, Bs, acc, wm, wn, g, tig);
        __syncthreads();
    }
    const float* bias = gs.B[z] ? gs.B[z] + (size_t)blk * CC : 0;
    float* Y = gs.Y[z] + (size_t)blk * NC;
    int epi = gs.epi[z];
    EPILOGUE_LOOP({
        float v = acc[i][j][r];
        if (bias) v += bias[n];
        if (epi == EPI_SIG) v = sigf(v);
        Y[(size_t)m * CC + n] = v;
    })
}

// gated out-proj, register double-buffered: A = attg*o; a += og * acc.
__global__ void tgemm_gateout(const float* __restrict__ attg, const float* __restrict__ o,
                              const float* __restrict__ Wm, const float* __restrict__ og) {
    __shared__ unsigned As[128][AP];
    __shared__ unsigned Bs[32][BP];
    int m0 = blockIdx.x * 128, n0 = blockIdx.y * 64;
    int tid = threadIdx.x, lane = tid & 31, w = tid >> 5;
    int g = lane >> 2, tig = lane & 3, wm = w >> 1, wn = w & 1;
    float acc[2][4][4] = {};
    ARegs ra; BRegs rb;
    loadA_mul(ra, attg, o, m0, 0, CC);
    loadB(rb, Wm, 0, n0, CC);
    #pragma unroll
    for (int c = 0; c < 4; c++) {
        storeA(As, ra);
        storeB(Bs, rb);
        __syncthreads();
        if (c < 3) {
            loadA_mul(ra, attg, o, m0, (c + 1) * 32, CC);
            loadB(rb, Wm, (c + 1) * 32, n0, CC);
        }
        compute32(As, Bs, acc, wm, wn, g, tig);
        __syncthreads();
    }
    EPILOGUE_LOOP({
        g_a[(size_t)m * CC + n] += og[(m & (NATOM - 1)) * CC + n] * acc[i][j][r];
    })
}

// transition dual gemm: hid = silu(X@Wa) * (X@Wb). Ncol=256, K=128.
__global__ void tgemm_dual(const float* __restrict__ X, const float* __restrict__ Wa,
                           const float* __restrict__ Wb) {
    __shared__ unsigned As[128][AP];
    __shared__ unsigned Bs[2][32][BP];
    const int N2 = 2 * CC;
    int m0 = blockIdx.x * 128, n0 = blockIdx.y * 64;
    int tid = threadIdx.x, lane = tid & 31, w = tid >> 5;
    int g = lane >> 2, tig = lane & 3, wm = w >> 1, wn = w & 1;
    float acc[2][2][4][4] = {};
    for (int k0 = 0; k0 < CC; k0 += 32) {
        stageA(As, X, m0, k0, CC);
        stageB(Bs[0], Wa, k0, n0, N2);
        stageB(Bs[1], Wb, k0, n0, N2);
        __syncthreads();
        compute32(As, Bs[0], acc[0], wm, wn, g, tig);
        compute32(As, Bs[1], acc[1], wm, wn, g, tig);
        __syncthreads();
    }
    EPILOGUE_LOOP({
        float h = acc[0][i][j][r];
        g_hid[(size_t)m * N2 + n] = h * sigf(h) * acc[1][i][j][r];
    })
}

// t_out: a += og * (hid @ W). K=256, Ncol=128.
__global__ void tgemm_tout(const float* __restrict__ Wm, const float* __restrict__ og) {
    __shared__ unsigned As[128][AP];
    __shared__ unsigned Bs[32][BP];
    const int K = 2 * CC;
    int m0 = blockIdx.x * 128, n0 = blockIdx.y * 64;
    int tid = threadIdx.x, lane = tid & 31, w = tid >> 5;
    int g = lane >> 2, tig = lane & 3, wm = w >> 1, wn = w & 1;
    float acc[2][4][4] = {};
    for (int k0 = 0; k0 < K; k0 += 32) {
        stageA(As, g_hid, m0, k0, K);
        stageB(Bs, Wm, k0, n0, CC);
        __syncthreads();
        compute32(As, Bs, acc, wm, wn, g, tig);
        __syncthreads();
    }
    EPILOGUE_LOOP({
        g_a[(size_t)m * CC + n] += og[(m & (NATOM - 1)) * CC + n] * acc[i][j][r];
    })
}

// token head: qtok = relu(a @ tok_w). Ncol=384, K=128.
__global__ void tgemm_tok(const float* __restrict__ Wm) {
    __shared__ unsigned As[128][AP];
    __shared__ unsigned Bs[32][BP];
    int m0 = blockIdx.x * 128, n0 = blockIdx.y * 64;
    int tid = threadIdx.x, lane = tid & 31, w = tid >> 5;
    int g = lane >> 2, tig = lane & 3, wm = w >> 1, wn = w & 1;
    float acc[2][4][4] = {};
    for (int k0 = 0; k0 < CC; k0 += 32) {
        stageA(As, g_a, m0, k0, CC);
        stageB(Bs, Wm, k0, n0, CTD);
        __syncthreads();
        compute32(As, Bs, acc, wm, wn, g, tig);
        __syncthreads();
    }
    EPILOGUE_LOOP({
        g_qtok[(size_t)m * CTD + n] = fmaxf(acc[i][j][r], 0.0f);
    })
}

// ---------------- LN kernels ----------------
// all 3 blocks in one launch: grid (NATOM, NBLK)
__global__ void k_ln_s3(const float* __restrict__ ap,
                        const float* __restrict__ w1b, const float* __restrict__ b1b,
                        const float* __restrict__ w2b, const float* __restrict__ b2b) {
    int n = blockIdx.x, blk = blockIdx.y, t = threadIdx.x;
    float x = ap[n * CC + t];
    float s1 = x, s2 = x * x;
    blockReduce2_128(s1, s2);
    float mu = s1 * (1.0f / CC);
    float var = s2 * (1.0f / CC) - mu * mu;
    float xn = (x - mu) * rsqrtf(var + EPS);
    const float* w1 = w1b + blk * CC; const float* b1 = b1b + blk * CC;
    const float* w2 = w2b + blk * CC; const float* b2 = b2b + blk * CC;
    g_sn [(size_t)blk * NC + n * CC + t] = xn * w1[t] + b1[t];
    g_sn2[(size_t)blk * NC + n * CC + t] = xn * w2[t] + b2[t];
}

__global__ void k_mod(const float* __restrict__ gate, const float* __restrict__ shift,
                      float* __restrict__ dst) {
    int n = blockIdx.x, s = blockIdx.y, t = threadIdx.x;
    float x = g_a[(size_t)(s * NATOM + n) * CC + t];
    float s1 = x, s2 = x * x;
    blockReduce2_128(s1, s2);
    float mu = s1 * (1.0f / CC);
    float var = s2 * (1.0f / CC) - mu * mu;
    float xn = (x - mu) * rsqrtf(var + EPS);
    dst[(size_t)(s * NATOM + n) * CC + t] = gate[n * CC + t] * xn + shift[n * CC + t];
}

// ---------------- pair bias (per block, into g_zb[blk]) ----------------
__global__ void k_zb(const float* __restrict__ pair, const float* __restrict__ lnw,
                     const float* __restrict__ lnb, const float* __restrict__ pw, int blk) {
    int idx = blockIdx.x * blockDim.x + threadIdx.x;
    if (idx >= NATOM * WIN) return;
    int q = idx >> 7, w = idx & 127;
    int m = (q >> 5) * 32 - 48 + w;
    float out[HH];
    #pragma unroll
    for (int h = 0; h < HH; h++) out[h] = 0.0f;
    if (m >= 0 && m < NATOM) {
        const float4* p = reinterpret_cast<const float4*>(pair + ((size_t)q * NATOM + m) * CPD);
        float v[CPD];
        float s1 = 0.0f, s2 = 0.0f;
        #pragma unroll
        for (int c4 = 0; c4 < 4; c4++) {
            float4 t = p[c4];
            v[c4*4+0] = t.x; v[c4*4+1] = t.y; v[c4*4+2] = t.z; v[c4*4+3] = t.w;
        }
        #pragma unroll
        for (int c = 0; c < CPD; c++) { s1 += v[c]; s2 += v[c] * v[c]; }
        float mu = s1 * (1.0f / CPD);
        float var = s2 * (1.0f / CPD) - mu * mu;
        float r = rsqrtf(var + EPS);
        #pragma unroll
        for (int c = 0; c < CPD; c++) {
            float xn = (v[c] - mu) * r * lnw[c] + lnb[c];
            #pragma unroll
            for (int h = 0; h < HH; h++) out[h] += xn * pw[c * HH + h];
        }
    }
    float* zb = g_zb + (size_t)blk * ZBS;
    #pragma unroll
    for (int h = 0; h < HH; h++)
        zb[((size_t)h * NATOM + q) * WIN + w] = out[h];
}

// ---------------- local attention ----------------
__global__ void k_attn(const float* __restrict__ mask, int blk) {
    int qb = blockIdx.x, h = blockIdx.y, s = blockIdx.z;
    __shared__ float qs[32][DHD];
    __shared__ float ks[WIN][DHD];
    __shared__ float vs[WIN][DHD];
    __shared__ float mb[WIN];
    int tid = threadIdx.x;
    int kbase = qb * 32 - 48;
    for (int i = tid; i < 32 * DHD; i += 128) {
        int qi = i / DHD, d = i % DHD;
        qs[qi][d] = g_q[((size_t)s * NATOM + qb * 32 + qi) * CC + h * DHD + d] * 0.25f;
    }
    for (int i = tid; i < WIN * DHD; i += 128) {
        int j = i / DHD, d = i % DHD;
        int m = kbase + j;
        float kk = 0.0f, vv = 0.0f;
        if (m >= 0 && m < NATOM) {
            kk = g_k[((size_t)s * NATOM + m) * CC + h * DHD + d];
            vv = g_v[((size_t)s * NATOM + m) * CC + h * DHD + d];
        }
        ks[j][d] = kk; vs[j][d] = vv;
    }
    for (int j = tid; j < WIN; j += 128) {
        int m = kbase + j;
        mb[j] = (m >= 0 && m < NATOM) ? (mask[m] - 1.0f) * 1e8f : -1e30f;
    }
    __syncthreads();

    int qi = tid >> 2;
    int lane = tid & 3;
    int qg = qb * 32 + qi;
    const float* zrow = g_zb + (size_t)blk * ZBS + ((size_t)h * NATOM + qg) * WIN;

    float lj[32];
    float mx = -1e30f;
    #pragma unroll
    for (int jj = 0; jj < 32; jj++) {
        int j = lane + jj * 4;
        float dot = 0.0f;
        #pragma unroll
        for (int d = 0; d < DHD; d++) dot += qs[qi][d] * ks[j][d];
        float l = dot + zrow[j] + mb[j];
        lj[jj] = l;
        mx = fmaxf(mx, l);
    }
    mx = fmaxf(mx, __shfl_xor_sync(0xffffffffu, mx, 1, 4));
    mx = fmaxf(mx, __shfl_xor_sync(0xffffffffu, mx, 2, 4));

    float sum = 0.0f;
    float oacc[DHD];
    #pragma unroll
    for (int d = 0; d < DHD; d++) oacc[d] = 0.0f;
    #pragma unroll
    for (int jj = 0; jj < 32; jj++) {
        int j = lane + jj * 4;
        float p = __expf(lj[jj] - mx);
        sum += p;
        #pragma unroll
        for (int d = 0; d < DHD; d++) oacc[d] += p * vs[j][d];
    }
    sum += __shfl_xor_sync(0xffffffffu, sum, 1, 4);
    sum += __shfl_xor_sync(0xffffffffu, sum, 2, 4);
    #pragma unroll
    for (int d = 0; d < DHD; d++) {
        oacc[d] += __shfl_xor_sync(0xffffffffu, oacc[d], 1, 4);
        oacc[d] += __shfl_xor_sync(0xffffffffu, oacc[d], 2, 4);
    }
    if (lane == 0) {
        float inv = 1.0f / sum;
        #pragma unroll
        for (int d = 0; d < DHD; d++)
            g_o[((size_t)s * NATOM + qg) * CC + h * DHD + d] = oacc[d] * inv;
    }
}

// ---------------- small kernels ----------------
__global__ void k_init_a(const float* __restrict__ src) {
    int i = blockIdx.x * blockDim.x + threadIdx.x;
    if (i < SNC) g_a[i] = src[i];
}

// token gather: out[s][t][:] = mean over {n: tok[n]==t} of qtok[s][n][:] (tok sorted).
__global__ void k_gather(const int* __restrict__ tok, float* __restrict__ out) {
    int t = blockIdx.x, s = blockIdx.y, c = threadIdx.x;
    __shared__ int slo, shi;
    if (c == 0) {
        int lo = 0, hi = NATOM;
        while (lo < hi) { int mid = (lo + hi) >> 1; if (tok[mid] < t) lo = mid + 1; else hi = mid; }
        slo = lo;
        int lo2 = lo, hi2 = NATOM;
        while (lo2 < hi2) { int mid = (lo2 + hi2) >> 1; if (tok[mid] < t + 1) lo2 = mid + 1; else hi2 = mid; }
        shi = lo2;
    }
    __syncthreads();
    int lo = slo, hi = shi;
    float sum = 0.0f;
    for (int n = lo; n < hi; n++)
        sum += g_qtok[((size_t)s * NATOM + n) * CTD + c];
    int cnt = hi - lo;
    out[((size_t)s * TT + t) * CTD + c] = sum / (float)(cnt > 0 ? cnt : 1);
}

// ---------------- host ----------------
extern "C" void kernel_launch(void* const* d_in, const int* in_sizes, int n_in,
                              void* d_out, int out_size) {
    const float* atom_single = (const float*)d_in[0];
    const float* atom_proj   = (const float*)d_in[1];
    const float* atom_pair   = (const float*)d_in[2];
    const float* mask        = (const float*)d_in[3];
    const int*   tok_idx     = (const int*)  d_in[4];
    const float* aln_s_w     = (const float*)d_in[5];
    const float* aln_s_b     = (const float*)d_in[6];
    const float* aln_gate_w  = (const float*)d_in[7];
    const float* aln_gate_b  = (const float*)d_in[8];
    const float* aln_shift_w = (const float*)d_in[9];
    const float* q_w         = (const float*)d_in[10];
    const float* q_b         = (const float*)d_in[11];
    const float* k_w         = (const float*)d_in[12];
    const float* v_w         = (const float*)d_in[13];
    const float* pair_ln_w   = (const float*)d_in[14];
    const float* pair_ln_b   = (const float*)d_in[15];
    const float* pair_w      = (const float*)d_in[16];
    const float* gate_w      = (const float*)d_in[17];
    const float* out_w       = (const float*)d_in[18];
    const float* og_w        = (const float*)d_in[19];
    const float* og_b        = (const float*)d_in[20];
    const float* t_aln_s_w   = (const float*)d_in[21];
    const float* t_aln_s_b   = (const float*)d_in[22];
    const float* t_aln_gate_w= (const float*)d_in[23];
    const float* t_aln_gate_b= (const float*)d_in[24];
    const float* t_aln_shift_w=(const float*)d_in[25];
    const float* t_a_w       = (const float*)d_in[26];
    const float* t_b_w       = (const float*)d_in[27];
    const float* t_out_w     = (const float*)d_in[28];
    const float* t_og_w      = (const float*)d_in[29];
    const float* t_og_b      = (const float*)d_in[30];
    const float* tok_w       = (const float*)d_in[31];
    float* out = (float*)d_out;

    static float *p_g1=0,*p_sh1=0,*p_og1=0,*p_g2=0,*p_sh2=0,*p_og2=0;
    static float *p_a1=0,*p_q=0,*p_k=0,*p_v=0,*p_attg=0,*p_o=0;
    static cudaStream_t sZ = 0, sS = 0;
    static cudaEvent_t evRoot = 0, evZ[NBLK], evB[NBLK];
    if (!p_g1) {
        cudaGetSymbolAddress((void**)&p_g1,   g_g1);
        cudaGetSymbolAddress((void**)&p_sh1,  g_sh1);
        cudaGetSymbolAddress((void**)&p_og1,  g_og1);
        cudaGetSymbolAddress((void**)&p_g2,   g_g2);
        cudaGetSymbolAddress((void**)&p_sh2,  g_sh2);
        cudaGetSymbolAddress((void**)&p_og2,  g_og2);
        cudaGetSymbolAddress((void**)&p_a1,   g_a1);
        cudaGetSymbolAddress((void**)&p_q,    g_q);
        cudaGetSymbolAddress((void**)&p_k,    g_k);
        cudaGetSymbolAddress((void**)&p_v,    g_v);
        cudaGetSymbolAddress((void**)&p_attg, g_attg);
        cudaGetSymbolAddress((void**)&p_o,    g_o);
        cudaStreamCreateWithFlags(&sZ, cudaStreamNonBlocking);
        cudaStreamCreateWithFlags(&sS, cudaStreamNonBlocking);
        cudaEventCreateWithFlags(&evRoot, cudaEventDisableTiming);
        for (int i = 0; i < NBLK; i++) {
            cudaEventCreateWithFlags(&evZ[i], cudaEventDisableTiming);
            cudaEventCreateWithFlags(&evB[i], cudaEventDisableTiming);
        }
    }

    const int M1 = NATOM;
    const int M2 = SS * NATOM;

    // ---- fork side branches from the capture stream ----
    cudaEventRecord(evRoot, 0);
    cudaStreamWaitEvent(sZ, evRoot, 0);
    cudaStreamWaitEvent(sS, evRoot, 0);

    // side stream Z: pair bias per block
    for (int i = 0; i < NBLK; i++) {
        k_zb<<<(NATOM * WIN + 255) / 256, 256, 0, sZ>>>(atom_pair,
                pair_ln_w + (size_t)i * CPD, pair_ln_b + (size_t)i * CPD,
                pair_w + (size_t)i * CPD * HH, i);
        cudaEventRecord(evZ[i], sZ);
    }

    // side stream S: dual-LN (all blocks) + per-block sn projections
    k_ln_s3<<<dim3(NATOM, NBLK), 128, 0, sS>>>(atom_proj, aln_s_w, aln_s_b,
                                               t_aln_s_w, t_aln_s_b);
    {
        GBS gs;
        gs.W[0]=aln_gate_w;  gs.B[0]=aln_gate_b;   gs.Y[0]=p_g1;  gs.epi[0]=EPI_SIG;
        gs.W[1]=aln_shift_w; gs.B[1]=0;            gs.Y[1]=p_sh1; gs.epi[1]=EPI_NONE;
        gs.W[2]=og_w;        gs.B[2]=og_b;         gs.Y[2]=p_og1; gs.epi[2]=EPI_SIG;
        gs.W[3]=t_aln_gate_w;gs.B[3]=t_aln_gate_b; gs.Y[3]=p_g2;  gs.epi[3]=EPI_SIG;
        gs.W[4]=t_aln_shift_w;gs.B[4]=0;           gs.Y[4]=p_sh2; gs.epi[4]=EPI_NONE;
        gs.W[5]=t_og_w;      gs.B[5]=t_og_b;       gs.Y[5]=p_og2; gs.epi[5]=EPI_SIG;
        for (int i = 0; i < NBLK; i++) {
            tgemm_sn_all<<<dim3(M1/128, CC/64, 6), 256, 0, sS>>>(gs, i);
            cudaEventRecord(evB[i], sS);
        }
    }

    // main stream: dependent chain
    k_init_a<<<(SNC + 255) / 256, 256>>>(atom_single);

    for (int i = 0; i < NBLK; i++) {
        const float* qwi = q_w  + (size_t)i * CC * CC;
        const float* qbi = q_b  + (size_t)i * CC;
        const float* kwi = k_w  + (size_t)i * CC * CC;
        const float* vwi = v_w  + (size_t)i * CC * CC;
        const float* gtw = gate_w + (size_t)i * CC * CC;
        const float* otw = out_w  + (size_t)i * CC * CC;
        const float* taw = t_a_w   + (size_t)i * CC * 2 * CC;
        const float* tbw = t_b_w   + (size_t)i * CC * 2 * CC;
        const float* tow = t_out_w + (size_t)i * 2 * CC * CC;

        cudaStreamWaitEvent(0, evB[i], 0);
        k_mod<<<dim3(NATOM, SS), 128>>>(p_g1 + (size_t)i * NC, p_sh1 + (size_t)i * NC, p_a1);

        {
            GB gb4;
            gb4.X[0]=p_a1; gb4.W[0]=qwi; gb4.B[0]=qbi; gb4.Y[0]=p_q;    gb4.epi[0]=EPI_NONE;
            gb4.X[1]=p_a1; gb4.W[1]=kwi; gb4.B[1]=0;   gb4.Y[1]=p_k;    gb4.epi[1]=EPI_NONE;
            gb4.X[2]=p_a1; gb4.W[2]=vwi; gb4.B[2]=0;   gb4.Y[2]=p_v;    gb4.epi[2]=EPI_NONE;
            gb4.X[3]=p_a1; gb4.W[3]=gtw; gb4.B[3]=0;   gb4.Y[3]=p_attg; gb4.epi[3]=EPI_SIG;
            gb4.X[4]=p_a1; gb4.W[4]=qwi; gb4.B[4]=0;   gb4.Y[4]=p_q;    gb4.epi[4]=EPI_NONE;
            gb4.X[5]=p_a1; gb4.W[5]=qwi; gb4.B[5]=0;   gb4.Y[5]=p_q;    gb4.epi[5]=EPI_NONE;
            tgemm_b<<<dim3(M2/128, CC/64, 4), 256>>>(gb4);
        }

        cudaStreamWaitEvent(0, evZ[i], 0);
        k_attn<<<dim3(NQB, HH, SS), 128>>>(mask, i);

        tgemm_gateout<<<dim3(M2/128, CC/64), 256>>>(p_attg, p_o, otw, p_og1 + (size_t)i * NC);

        k_mod<<<dim3(NATOM, SS), 128>>>(p_g2 + (size_t)i * NC, p_sh2 + (size_t)i * NC, p_a1);
        tgemm_dual<<<dim3(M2/128, (2*CC)/64), 256>>>(p_a1, taw, tbw);
        tgemm_tout<<<dim3(M2/128, CC/64), 256>>>(tow, p_og2 + (size_t)i * NC);
    }

    // token head + sorted-gather aggregation
    tgemm_tok<<<dim3(M2/128, CTD/64), 256>>>(tok_w);
    k_gather<<<dim3(TT, SS), CTD>>>(tok_idx, out);
}

// round 14
// speedup vs baseline: 1.0062x; 1.0062x over previous
#include <cuda_runtime.h>
#include <math.h>
#include <stdint.h>

#define SS 2
#define NATOM 2048
#define CC 128
#define HH 8
#define DHD 16
#define CPD 16
#define TT 512
#define CTD 384
#define NBLK 3
#define WIN 128
#define NQB (NATOM/32)
#define EPS 1e-5f
#define SNC (SS*NATOM*CC)
#define NC (NATOM*CC)
#define ZBS (HH*NATOM*WIN)

#define EPI_NONE 0
#define EPI_SIG  1

#define AP 36
#define BP 72

// ---------------- scratch ----------------
__device__ __align__(16) float g_sn  [NBLK*NC];
__device__ __align__(16) float g_sn2 [NBLK*NC];
__device__ __align__(16) float g_g1  [NBLK*NC];
__device__ __align__(16) float g_sh1 [NBLK*NC];
__device__ __align__(16) float g_og1 [NBLK*NC];
__device__ __align__(16) float g_g2  [NBLK*NC];
__device__ __align__(16) float g_sh2 [NBLK*NC];
__device__ __align__(16) float g_og2 [NBLK*NC];
__device__ __align__(16) float g_a   [SNC];
__device__ __align__(16) float g_a1  [SNC];
__device__ __align__(16) float g_q   [SNC];
__device__ __align__(16) float g_k   [SNC];
__device__ __align__(16) float g_v   [SNC];
__device__ __align__(16) float g_attg[SNC];
__device__ __align__(16) float g_o   [SNC];
__device__ __align__(16) float g_zb  [NBLK*ZBS];
__device__ __align__(16) float g_hid [SS*NATOM*2*CC];
__device__ __align__(16) float g_qtok[SS*NATOM*CTD];

// ---------------- helpers ----------------
__device__ __forceinline__ void blockReduce2_128(float& a, float& b) {
    #pragma unroll
    for (int o = 16; o; o >>= 1) {
        a += __shfl_xor_sync(0xffffffffu, a, o);
        b += __shfl_xor_sync(0xffffffffu, b, o);
    }
    __shared__ float sa[4], sb[4];
    int w = threadIdx.x >> 5;
    if ((threadIdx.x & 31) == 0) { sa[w] = a; sb[w] = b; }
    __syncthreads();
    a = sa[0] + sa[1] + sa[2] + sa[3];
    b = sb[0] + sb[1] + sb[2] + sb[3];
}

__device__ __forceinline__ float sigf(float x) { return 1.0f / (1.0f + __expf(-x)); }

__device__ __forceinline__ unsigned f2tf(float f) {
    unsigned u; asm("cvt.rna.tf32.f32 %0, %1;" : "=r"(u) : "f"(f)); return u;
}

__device__ __forceinline__ void mma_tf32(float (&d)[4], const unsigned (&a)[4], const unsigned (&b)[2]) {
    asm volatile(
        "mma.sync.aligned.m16n8k8.row.col.f32.tf32.tf32.f32 "
        "{%0,%1,%2,%3}, {%4,%5,%6,%7}, {%8,%9}, {%0,%1,%2,%3};\n"
        : "+f"(d[0]), "+f"(d[1]), "+f"(d[2]), "+f"(d[3])
        : "r"(a[0]), "r"(a[1]), "r"(a[2]), "r"(a[3]), "r"(b[0]), "r"(b[1]));
}

// ---------------- GEMM building blocks ----------------
struct ARegs { float4 v[4]; };
struct BRegs { float4 v[2]; };

__device__ __forceinline__ void loadA(ARegs& ra, const float* __restrict__ X,
                                      int m0, int k0, int ld) {
    int t = threadIdx.x;
    int r = t >> 1, cb = (t & 1) * 16;
    const float4* src = reinterpret_cast<const float4*>(X + (size_t)(m0 + r) * ld + k0 + cb);
    #pragma unroll
    for (int i = 0; i < 4; i++) ra.v[i] = src[i];
}

__device__ __forceinline__ void loadA_mul(ARegs& ra, const float* __restrict__ X1,
                                          const float* __restrict__ X2, int m0, int k0, int ld) {
    int t = threadIdx.x;
    int r = t >> 1, cb = (t & 1) * 16;
    size_t base = (size_t)(m0 + r) * ld + k0 + cb;
    const float4* s1 = reinterpret_cast<const float4*>(X1 + base);
    const float4* s2 = reinterpret_cast<const float4*>(X2 + base);
    #pragma unroll
    for (int i = 0; i < 4; i++) {
        float4 a = s1[i], b = s2[i];
        ra.v[i] = make_float4(a.x*b.x, a.y*b.y, a.z*b.z, a.w*b.w);
    }
}

__device__ __forceinline__ void storeA(unsigned (*As)[AP], const ARegs& ra) {
    int t = threadIdx.x;
    int r = t >> 1, cb = (t & 1) * 16;
    #pragma unroll
    for (int i = 0; i < 4; i++) {
        float4 v = ra.v[i];
        uint4 u = make_uint4(f2tf(v.x), f2tf(v.y), f2tf(v.z), f2tf(v.w));
        *reinterpret_cast<uint4*>(&As[r][cb + 4*i]) = u;
    }
}

__device__ __forceinline__ void loadB(BRegs& rb, const float* __restrict__ W,
                                      int k0, int n0, int ld) {
    int t = threadIdx.x;
    int k = t >> 3, nb = (t & 7) * 8;
    const float4* src = reinterpret_cast<const float4*>(W + (size_t)(k0 + k) * ld + n0 + nb);
    rb.v[0] = src[0]; rb.v[1] = src[1];
}

__device__ __forceinline__ void storeB(unsigned (*Bs)[BP], const BRegs& rb) {
    int t = threadIdx.x;
    int k = t >> 3, nb = (t & 7) * 8;
    float4 v0 = rb.v[0], v1 = rb.v[1];
    *reinterpret_cast<uint4*>(&Bs[k][nb])     = make_uint4(f2tf(v0.x), f2tf(v0.y), f2tf(v0.z), f2tf(v0.w));
    *reinterpret_cast<uint4*>(&Bs[k][nb + 4]) = make_uint4(f2tf(v1.x), f2tf(v1.y), f2tf(v1.z), f2tf(v1.w));
}

__device__ __forceinline__ void stageA(unsigned (*As)[AP], const float* __restrict__ X,
                                       int m0, int k0, int ld) {
    ARegs ra; loadA(ra, X, m0, k0, ld); storeA(As, ra);
}
__device__ __forceinline__ void stageB(unsigned (*Bs)[BP], const float* __restrict__ W,
                                       int k0, int n0, int ld) {
    BRegs rb; loadB(rb, W, k0, n0, ld); storeB(Bs, rb);
}

__device__ __forceinline__ void compute32(const unsigned (*As)[AP], const unsigned (*Bs)[BP],
                                          float (*acc)[4][4], int wm, int wn, int g, int tig) {
    #pragma unroll
    for (int ks = 0; ks < 4; ks++) {
        int k8 = ks * 8;
        unsigned a[2][4], b[4][2];
        #pragma unroll
        for (int i = 0; i < 2; i++) {
            int rb = wm * 32 + i * 16;
            a[i][0] = As[rb + g    ][k8 + tig];
            a[i][1] = As[rb + g + 8][k8 + tig];
            a[i][2] = As[rb + g    ][k8 + tig + 4];
            a[i][3] = As[rb + g + 8][k8 + tig + 4];
        }
        #pragma unroll
        for (int j = 0; j < 4; j++) {
            int nb = wn * 32 + j * 8;
            b[j][0] = Bs[k8 + tig    ][nb + g];
            b[j][1] = Bs[k8 + tig + 4][nb + g];
        }
        #pragma unroll
        for (int i = 0; i < 2; i++)
            #pragma unroll
            for (int j = 0; j < 4; j++)
                mma_tf32(acc[i][j], a[i], b[j]);
    }
}

#define EPILOGUE_LOOP(BODY)                                                    \
    _Pragma("unroll")                                                          \
    for (int i = 0; i < 2; i++) {                                              \
        _Pragma("unroll")                                                      \
        for (int j = 0; j < 4; j++) {                                          \
            _Pragma("unroll")                                                  \
            for (int r = 0; r < 4; r++) {                                      \
                int m = m0 + wm*32 + i*16 + g + ((r >> 1) ? 8 : 0);            \
                int n = n0 + wn*32 + j*8 + 2*tig + (r & 1);                    \
                BODY                                                           \
            }                                                                  \
        }                                                                      \
    }

struct GB {
    const float* X[6];
    const float* W[6];
    const float* B[6];
    float*       Y[6];
    int          epi[6];
};

// batched gemm, register double-buffered. Ncol=K=CC.
__global__ void tgemm_b(GB gb) {
    __shared__ unsigned As[128][AP];
    __shared__ unsigned Bs[32][BP];
    int z = blockIdx.z;
    const float* X = gb.X[z];
    const float* W = gb.W[z];
    int m0 = blockIdx.x * 128, n0 = blockIdx.y * 64;
    int tid = threadIdx.x, lane = tid & 31, w = tid >> 5;
    int g = lane >> 2, tig = lane & 3, wm = w >> 1, wn = w & 1;
    float acc[2][4][4] = {};
    ARegs ra; BRegs rb;
    loadA(ra, X, m0, 0, CC);
    loadB(rb, W, 0, n0, CC);
    #pragma unroll
    for (int c = 0; c < 4; c++) {
        storeA(As, ra);
        storeB(Bs, rb);
        __syncthreads();
        if (c < 3) {
            loadA(ra, X, m0, (c + 1) * 32, CC);
            loadB(rb, W, (c + 1) * 32, n0, CC);
        }
        compute32(As, Bs, acc, wm, wn, g, tig);
        __syncthreads();
    }
    const float* bias = gb.B[z];
    float* Y = gb.Y[z];
    int epi = gb.epi[z];
    EPILOGUE_LOOP({
        float v = acc[i][j][r];
        if (bias) v += bias[n];
        if (epi == EPI_SIG) v = sigf(v);
        Y[(size_t)m * CC + n] = v;
    })
}

// sn-projection batch for ONE block: z = 0..5, base pointers offset by blk.
struct GBS {
    const float* W[6];
    const float* B[6];
    float*       Y[6];
    int          epi[6];
};

__global__ void tgemm_sn_all(GBS gs, int blk) {
    __shared__ unsigned As[128][AP];
    __shared__ unsigned Bs[32][BP];
    int z = blockIdx.z;
    const float* X = (z < 3 ? g_sn : g_sn2) + (size_t)blk * NC;
    const float* W = gs.W[z] + (size_t)blk * CC * CC;
    int m0 = blockIdx.x * 128, n0 = blockIdx.y * 64;
    int tid = threadIdx.x, lane = tid & 31, w = tid >> 5;
    int g = lane >> 2, tig = lane & 3, wm = w >> 1, wn = w & 1;
    float acc[2][4][4] = {};
    ARegs ra; BRegs rb;
    loadA(ra, X, m0, 0, CC);
    loadB(rb, W, 0, n0, CC);
    #pragma unroll
    for (int c = 0; c < 4; c++) {
        storeA(As, ra);
        storeB(Bs, rb);
        __syncthreads();
        if (c < 3) {
            loadA(ra, X, m0, (c + 1) * 32, CC);
            loadB(rb, W, (c + 1) * 32, n0, CC);
        }
        compute32(As, Bs, acc, wm, wn, g, tig);
        __syncthreads();
    }
    const float* bias = gs.B[z] ? gs.B[z] + (size_t)blk * CC : 0;
    float* Y = gs.Y[z] + (size_t)blk * NC;
    int epi = gs.epi[z];
    EPILOGUE_LOOP({
        float v = acc[i][j][r];
        if (bias) v += bias[n];
        if (epi == EPI_SIG) v = sigf(v);
        Y[(size_t)m * CC + n] = v;
    })
}

// gated out-proj, register double-buffered: A = attg*o; a += og * acc.
__global__ void tgemm_gateout(const float* __restrict__ attg, const float* __restrict__ o,
                              const float* __restrict__ Wm, const float* __restrict__ og) {
    __shared__ unsigned As[128][AP];
    __shared__ unsigned Bs[32][BP];
    int m0 = blockIdx.x * 128, n0 = blockIdx.y * 64;
    int tid = threadIdx.x, lane = tid & 31, w = tid >> 5;
    int g = lane >> 2, tig = lane & 3, wm = w >> 1, wn = w & 1;
    float acc[2][4][4] = {};
    ARegs ra; BRegs rb;
    loadA_mul(ra, attg, o, m0, 0, CC);
    loadB(rb, Wm, 0, n0, CC);
    #pragma unroll
    for (int c = 0; c < 4; c++) {
        storeA(As, ra);
        storeB(Bs, rb);
        __syncthreads();
        if (c < 3) {
            loadA_mul(ra, attg, o, m0, (c + 1) * 32, CC);
            loadB(rb, Wm, (c + 1) * 32, n0, CC);
        }
        compute32(As, Bs, acc, wm, wn, g, tig);
        __syncthreads();
    }
    EPILOGUE_LOOP({
        g_a[(size_t)m * CC + n] += og[(m & (NATOM - 1)) * CC + n] * acc[i][j][r];
    })
}

// transition dual gemm: hid = silu(X@Wa) * (X@Wb). Ncol=256, K=128.
__global__ void tgemm_dual(const float* __restrict__ X, const float* __restrict__ Wa,
                           const float* __restrict__ Wb) {
    __shared__ unsigned As[128][AP];
    __shared__ unsigned Bs[2][32][BP];
    const int N2 = 2 * CC;
    int m0 = blockIdx.x * 128, n0 = blockIdx.y * 64;
    int tid = threadIdx.x, lane = tid & 31, w = tid >> 5;
    int g = lane >> 2, tig = lane & 3, wm = w >> 1, wn = w & 1;
    float acc[2][2][4][4] = {};
    for (int k0 = 0; k0 < CC; k0 += 32) {
        stageA(As, X, m0, k0, CC);
        stageB(Bs[0], Wa, k0, n0, N2);
        stageB(Bs[1], Wb, k0, n0, N2);
        __syncthreads();
        compute32(As, Bs[0], acc[0], wm, wn, g, tig);
        compute32(As, Bs[1], acc[1], wm, wn, g, tig);
        __syncthreads();
    }
    EPILOGUE_LOOP({
        float h = acc[0][i][j][r];
        g_hid[(size_t)m * N2 + n] = h * sigf(h) * acc[1][i][j][r];
    })
}

// t_out: a += og * (hid @ W). K=256, Ncol=128.
__global__ void tgemm_tout(const float* __restrict__ Wm, const float* __restrict__ og) {
    __shared__ unsigned As[128][AP];
    __shared__ unsigned Bs[32][BP];
    const int K = 2 * CC;
    int m0 = blockIdx.x * 128, n0 = blockIdx.y * 64;
    int tid = threadIdx.x, lane = tid & 31, w = tid >> 5;
    int g = lane >> 2, tig = lane & 3, wm = w >> 1, wn = w & 1;
    float acc[2][4][4] = {};
    for (int k0 = 0; k0 < K; k0 += 32) {
        stageA(As, g_hid, m0, k0, K);
        stageB(Bs, Wm, k0, n0, CC);
        __syncthreads();
        compute32(As, Bs, acc, wm, wn, g, tig);
        __syncthreads();
    }
    EPILOGUE_LOOP({
        g_a[(size_t)m * CC + n] += og[(m & (NATOM - 1)) * CC + n] * acc[i][j][r];
    })
}

// token head: qtok = relu(a @ tok_w). Ncol=384, K=128.
__global__ void tgemm_tok(const float* __restrict__ Wm) {
    __shared__ unsigned As[128][AP];
    __shared__ unsigned Bs[32][BP];
    int m0 = blockIdx.x * 128, n0 = blockIdx.y * 64;
    int tid = threadIdx.x, lane = tid & 31, w = tid >> 5;
    int g = lane >> 2, tig = lane & 3, wm = w >> 1, wn = w & 1;
    float acc[2][4][4] = {};
    for (int k0 = 0; k0 < CC; k0 += 32) {
        stageA(As, g_a, m0, k0, CC);
        stageB(Bs, Wm, k0, n0, CTD);
        __syncthreads();
        compute32(As, Bs, acc, wm, wn, g, tig);
        __syncthreads();
    }
    EPILOGUE_LOOP({
        g_qtok[(size_t)m * CTD + n] = fmaxf(acc[i][j][r], 0.0f);
    })
}

// ---------------- LN kernels ----------------
// all 3 blocks in one launch: grid (NATOM, NBLK)
__global__ void k_ln_s3(const float* __restrict__ ap,
                        const float* __restrict__ w1b, const float* __restrict__ b1b,
                        const float* __restrict__ w2b, const float* __restrict__ b2b) {
    int n = blockIdx.x, blk = blockIdx.y, t = threadIdx.x;
    float x = ap[n * CC + t];
    float s1 = x, s2 = x * x;
    blockReduce2_128(s1, s2);
    float mu = s1 * (1.0f / CC);
    float var = s2 * (1.0f / CC) - mu * mu;
    float xn = (x - mu) * rsqrtf(var + EPS);
    const float* w1 = w1b + blk * CC; const float* b1 = b1b + blk * CC;
    const float* w2 = w2b + blk * CC; const float* b2 = b2b + blk * CC;
    g_sn [(size_t)blk * NC + n * CC + t] = xn * w1[t] + b1[t];
    g_sn2[(size_t)blk * NC + n * CC + t] = xn * w2[t] + b2[t];
}

__global__ void k_mod(const float* __restrict__ gate, const float* __restrict__ shift,
                      float* __restrict__ dst) {
    int n = blockIdx.x, s = blockIdx.y, t = threadIdx.x;
    float x = g_a[(size_t)(s * NATOM + n) * CC + t];
    float s1 = x, s2 = x * x;
    blockReduce2_128(s1, s2);
    float mu = s1 * (1.0f / CC);
    float var = s2 * (1.0f / CC) - mu * mu;
    float xn = (x - mu) * rsqrtf(var + EPS);
    dst[(size_t)(s * NATOM + n) * CC + t] = gate[n * CC + t] * xn + shift[n * CC + t];
}

// ---------------- pair bias (per block, into g_zb[blk]) ----------------
__global__ void k_zb(const float* __restrict__ pair, const float* __restrict__ lnw,
                     const float* __restrict__ lnb, const float* __restrict__ pw, int blk) {
    int idx = blockIdx.x * blockDim.x + threadIdx.x;
    if (idx >= NATOM * WIN) return;
    int q = idx >> 7, w = idx & 127;
    int m = (q >> 5) * 32 - 48 + w;
    float out[HH];
    #pragma unroll
    for (int h = 0; h < HH; h++) out[h] = 0.0f;
    if (m >= 0 && m < NATOM) {
        const float4* p = reinterpret_cast<const float4*>(pair + ((size_t)q * NATOM + m) * CPD);
        float v[CPD];
        float s1 = 0.0f, s2 = 0.0f;
        #pragma unroll
        for (int c4 = 0; c4 < 4; c4++) {
            float4 t = p[c4];
            v[c4*4+0] = t.x; v[c4*4+1] = t.y; v[c4*4+2] = t.z; v[c4*4+3] = t.w;
        }
        #pragma unroll
        for (int c = 0; c < CPD; c++) { s1 += v[c]; s2 += v[c] * v[c]; }
        float mu = s1 * (1.0f / CPD);
        float var = s2 * (1.0f / CPD) - mu * mu;
        float r = rsqrtf(var + EPS);
        #pragma unroll
        for (int c = 0; c < CPD; c++) {
            float xn = (v[c] - mu) * r * lnw[c] + lnb[c];
            #pragma unroll
            for (int h = 0; h < HH; h++) out[h] += xn * pw[c * HH + h];
        }
    }
    float* zb = g_zb + (size_t)blk * ZBS;
    #pragma unroll
    for (int h = 0; h < HH; h++)
        zb[((size_t)h * NATOM + q) * WIN + w] = out[h];
}

// ---------------- local attention ----------------
__global__ void k_attn(const float* __restrict__ mask, int blk) {
    int qb = blockIdx.x, h = blockIdx.y, s = blockIdx.z;
    __shared__ float qs[32][DHD];
    __shared__ float ks[WIN][DHD];
    __shared__ float vs[WIN][DHD];
    __shared__ float mb[WIN];
    int tid = threadIdx.x;
    int kbase = qb * 32 - 48;
    for (int i = tid; i < 32 * DHD; i += 128) {
        int qi = i / DHD, d = i % DHD;
        qs[qi][d] = g_q[((size_t)s * NATOM + qb * 32 + qi) * CC + h * DHD + d] * 0.25f;
    }
    for (int i = tid; i < WIN * DHD; i += 128) {
        int j = i / DHD, d = i % DHD;
        int m = kbase + j;
        float kk = 0.0f, vv = 0.0f;
        if (m >= 0 && m < NATOM) {
            kk = g_k[((size_t)s * NATOM + m) * CC + h * DHD + d];
            vv = g_v[((size_t)s * NATOM + m) * CC + h * DHD + d];
        }
        ks[j][d] = kk; vs[j][d] = vv;
    }
    for (int j = tid; j < WIN; j += 128) {
        int m = kbase + j;
        mb[j] = (m >= 0 && m < NATOM) ? (mask[m] - 1.0f) * 1e8f : -1e30f;
    }
    __syncthreads();

    int qi = tid >> 2;
    int lane = tid & 3;
    int qg = qb * 32 + qi;
    const float* zrow = g_zb + (size_t)blk * ZBS + ((size_t)h * NATOM + qg) * WIN;

    float lj[32];
    float mx = -1e30f;
    #pragma unroll
    for (int jj = 0; jj < 32; jj++) {
        int j = lane + jj * 4;
        float dot = 0.0f;
        #pragma unroll
        for (int d = 0; d < DHD; d++) dot += qs[qi][d] * ks[j][d];
        float l = dot + zrow[j] + mb[j];
        lj[jj] = l;
        mx = fmaxf(mx, l);
    }
    mx = fmaxf(mx, __shfl_xor_sync(0xffffffffu, mx, 1, 4));
    mx = fmaxf(mx, __shfl_xor_sync(0xffffffffu, mx, 2, 4));

    float sum = 0.0f;
    float oacc[DHD];
    #pragma unroll
    for (int d = 0; d < DHD; d++) oacc[d] = 0.0f;
    #pragma unroll
    for (int jj = 0; jj < 32; jj++) {
        int j = lane + jj * 4;
        float p = __expf(lj[jj] - mx);
        sum += p;
        #pragma unroll
        for (int d = 0; d < DHD; d++) oacc[d] += p * vs[j][d];
    }
    sum += __shfl_xor_sync(0xffffffffu, sum, 1, 4);
    sum += __shfl_xor_sync(0xffffffffu, sum, 2, 4);
    #pragma unroll
    for (int d = 0; d < DHD; d++) {
        oacc[d] += __shfl_xor_sync(0xffffffffu, oacc[d], 1, 4);
        oacc[d] += __shfl_xor_sync(0xffffffffu, oacc[d], 2, 4);
    }
    if (lane == 0) {
        float inv = 1.0f / sum;
        #pragma unroll
        for (int d = 0; d < DHD; d++)
            g_o[((size_t)s * NATOM + qg) * CC + h * DHD + d] = oacc[d] * inv;
    }
}

// ---------------- small kernels ----------------
__global__ void k_init_a(const float* __restrict__ src) {
    int i = blockIdx.x * blockDim.x + threadIdx.x;
    if (i < SNC) g_a[i] = src[i];
}

// token gather: out[s][t][:] = mean over {n: tok[n]==t} of qtok[s][n][:] (tok sorted).
__global__ void k_gather(const int* __restrict__ tok, float* __restrict__ out) {
    int t = blockIdx.x, s = blockIdx.y, c = threadIdx.x;
    __shared__ int slo, shi;
    if (c == 0) {
        int lo = 0, hi = NATOM;
        while (lo < hi) { int mid = (lo + hi) >> 1; if (tok[mid] < t) lo = mid + 1; else hi = mid; }
        slo = lo;
        int lo2 = lo, hi2 = NATOM;
        while (lo2 < hi2) { int mid = (lo2 + hi2) >> 1; if (tok[mid] < t + 1) lo2 = mid + 1; else hi2 = mid; }
        shi = lo2;
    }
    __syncthreads();
    int lo = slo, hi = shi;
    float sum = 0.0f;
    for (int n = lo; n < hi; n++)
        sum += g_qtok[((size_t)s * NATOM + n) * CTD + c];
    int cnt = hi - lo;
    out[((size_t)s * TT + t) * CTD + c] = sum / (float)(cnt > 0 ? cnt : 1);
}

// ---------------- host ----------------
extern "C" void kernel_launch(void* const* d_in, const int* in_sizes, int n_in,
                              void* d_out, int out_size) {
    const float* atom_single = (const float*)d_in[0];
    const float* atom_proj   = (const float*)d_in[1];
    const float* atom_pair   = (const float*)d_in[2];
    const float* mask        = (const float*)d_in[3];
    const int*   tok_idx     = (const int*)  d_in[4];
    const float* aln_s_w     = (const float*)d_in[5];
    const float* aln_s_b     = (const float*)d_in[6];
    const float* aln_gate_w  = (const float*)d_in[7];
    const float* aln_gate_b  = (const float*)d_in[8];
    const float* aln_shift_w = (const float*)d_in[9];
    const float* q_w         = (const float*)d_in[10];
    const float* q_b         = (const float*)d_in[11];
    const float* k_w         = (const float*)d_in[12];
    const float* v_w         = (const float*)d_in[13];
    const float* pair_ln_w   = (const float*)d_in[14];
    const float* pair_ln_b   = (const float*)d_in[15];
    const float* pair_w      = (const float*)d_in[16];
    const float* gate_w      = (const float*)d_in[17];
    const float* out_w       = (const float*)d_in[18];
    const float* og_w        = (const float*)d_in[19];
    const float* og_b        = (const float*)d_in[20];
    const float* t_aln_s_w   = (const float*)d_in[21];
    const float* t_aln_s_b   = (const float*)d_in[22];
    const float* t_aln_gate_w= (const float*)d_in[23];
    const float* t_aln_gate_b= (const float*)d_in[24];
    const float* t_aln_shift_w=(const float*)d_in[25];
    const float* t_a_w       = (const float*)d_in[26];
    const float* t_b_w       = (const float*)d_in[27];
    const float* t_out_w     = (const float*)d_in[28];
    const float* t_og_w      = (const float*)d_in[29];
    const float* t_og_b      = (const float*)d_in[30];
    const float* tok_w       = (const float*)d_in[31];
    float* out = (float*)d_out;

    static float *p_g1=0,*p_sh1=0,*p_og1=0,*p_g2=0,*p_sh2=0,*p_og2=0;
    static float *p_a1=0,*p_q=0,*p_k=0,*p_v=0,*p_attg=0,*p_o=0;
    static cudaStream_t sZ = 0, sS = 0;
    static cudaEvent_t evRoot = 0, evZ[NBLK], evB[NBLK];
    if (!p_g1) {
        cudaGetSymbolAddress((void**)&p_g1,   g_g1);
        cudaGetSymbolAddress((void**)&p_sh1,  g_sh1);
        cudaGetSymbolAddress((void**)&p_og1,  g_og1);
        cudaGetSymbolAddress((void**)&p_g2,   g_g2);
        cudaGetSymbolAddress((void**)&p_sh2,  g_sh2);
        cudaGetSymbolAddress((void**)&p_og2,  g_og2);
        cudaGetSymbolAddress((void**)&p_a1,   g_a1);
        cudaGetSymbolAddress((void**)&p_q,    g_q);
        cudaGetSymbolAddress((void**)&p_k,    g_k);
        cudaGetSymbolAddress((void**)&p_v,    g_v);
        cudaGetSymbolAddress((void**)&p_attg, g_attg);
        cudaGetSymbolAddress((void**)&p_o,    g_o);
        cudaStreamCreateWithFlags(&sZ, cudaStreamNonBlocking);
        cudaStreamCreateWithFlags(&sS, cudaStreamNonBlocking);
        cudaEventCreateWithFlags(&evRoot, cudaEventDisableTiming);
        for (int i = 0; i < NBLK; i++) {
            cudaEventCreateWithFlags(&evZ[i], cudaEventDisableTiming);
            cudaEventCreateWithFlags(&evB[i], cudaEventDisableTiming);
        }
    }

    const int M1 = NATOM;
    const int M2 = SS * NATOM;

    // ---- fork side branches from the capture stream ----
    cudaEventRecord(evRoot, 0);
    cudaStreamWaitEvent(sZ, evRoot, 0);
    cudaStreamWaitEvent(sS, evRoot, 0);

    // side stream Z: pair bias per block
    for (int i = 0; i < NBLK; i++) {
        k_zb<<<(NATOM * WIN + 255) / 256, 256, 0, sZ>>>(atom_pair,
                pair_ln_w + (size_t)i * CPD, pair_ln_b + (size_t)i * CPD,
                pair_w + (size_t)i * CPD * HH, i);
        cudaEventRecord(evZ[i], sZ);
    }

    // side stream S: dual-LN (all blocks) + per-block sn projections
    k_ln_s3<<<dim3(NATOM, NBLK), 128, 0, sS>>>(atom_proj, aln_s_w, aln_s_b,
                                               t_aln_s_w, t_aln_s_b);
    {
        GBS gs;
        gs.W[0]=aln_gate_w;  gs.B[0]=aln_gate_b;   gs.Y[0]=p_g1;  gs.epi[0]=EPI_SIG;
        gs.W[1]=aln_shift_w; gs.B[1]=0;            gs.Y[1]=p_sh1; gs.epi[1]=EPI_NONE;
        gs.W[2]=og_w;        gs.B[2]=og_b;         gs.Y[2]=p_og1; gs.epi[2]=EPI_SIG;
        gs.W[3]=t_aln_gate_w;gs.B[3]=t_aln_gate_b; gs.Y[3]=p_g2;  gs.epi[3]=EPI_SIG;
        gs.W[4]=t_aln_shift_w;gs.B[4]=0;           gs.Y[4]=p_sh2; gs.epi[4]=EPI_NONE;
        gs.W[5]=t_og_w;      gs.B[5]=t_og_b;       gs.Y[5]=p_og2; gs.epi[5]=EPI_SIG;
        for (int i = 0; i < NBLK; i++) {
            tgemm_sn_all<<<dim3(M1/128, CC/64, 6), 256, 0, sS>>>(gs, i);
            cudaEventRecord(evB[i], sS);
        }
    }

    // main stream: dependent chain
    k_init_a<<<(SNC + 255) / 256, 256>>>(atom_single);

    for (int i = 0; i < NBLK; i++) {
        const float* qwi = q_w  + (size_t)i * CC * CC;
        const float* qbi = q_b  + (size_t)i * CC;
        const float* kwi = k_w  + (size_t)i * CC * CC;
        const float* vwi = v_w  + (size_t)i * CC * CC;
        const float* gtw = gate_w + (size_t)i * CC * CC;
        const float* otw = out_w  + (size_t)i * CC * CC;
        const float* taw = t_a_w   + (size_t)i * CC * 2 * CC;
        const float* tbw = t_b_w   + (size_t)i * CC * 2 * CC;
        const float* tow = t_out_w + (size_t)i * 2 * CC * CC;

        cudaStreamWaitEvent(0, evB[i], 0);
        k_mod<<<dim3(NATOM, SS), 128>>>(p_g1 + (size_t)i * NC, p_sh1 + (size_t)i * NC, p_a1);

        {
            GB gb4;
            gb4.X[0]=p_a1; gb4.W[0]=qwi; gb4.B[0]=qbi; gb4.Y[0]=p_q;    gb4.epi[0]=EPI_NONE;
            gb4.X[1]=p_a1; gb4.W[1]=kwi; gb4.B[1]=0;   gb4.Y[1]=p_k;    gb4.epi[1]=EPI_NONE;
            gb4.X[2]=p_a1; gb4.W[2]=vwi; gb4.B[2]=0;   gb4.Y[2]=p_v;    gb4.epi[2]=EPI_NONE;
            gb4.X[3]=p_a1; gb4.W[3]=gtw; gb4.B[3]=0;   gb4.Y[3]=p_attg; gb4.epi[3]=EPI_SIG;
            gb4.X[4]=p_a1; gb4.W[4]=qwi; gb4.B[4]=0;   gb4.Y[4]=p_q;    gb4.epi[4]=EPI_NONE;
            gb4.X[5]=p_a1; gb4.W[5]=qwi; gb4.B[5]=0;   gb4.Y[5]=p_q;    gb4.epi[5]=EPI_NONE;
            tgemm_b<<<dim3(M2/128, CC/64, 4), 256>>>(gb4);
        }

        cudaStreamWaitEvent(0, evZ[i], 0);
        k_attn<<<dim3(NQB, HH, SS), 128>>>(mask, i);

        tgemm_gateout<<<dim3(M2/128, CC/64), 256>>>(p_attg, p_o, otw, p_og1 + (size_t)i * NC);

        k_mod<<<dim3(NATOM, SS), 128>>>(p_g2 + (size_t)i * NC, p_sh2 + (size_t)i * NC, p_a1);
        tgemm_dual<<<dim3(M2/128, (2*CC)/64), 256>>>(p_a1, taw, tbw);
        tgemm_tout<<<dim3(M2/128, CC/64), 256>>>(tow, p_og2 + (size_t)i * NC);
    }

    // token head + sorted-gather aggregation
    tgemm_tok<<<dim3(M2/128, CTD/64), 256>>>(tok_w);
    k_gather<<<dim3(TT, SS), CTD>>>(tok_idx, out);
}